// round 8
// baseline (speedup 1.0000x reference)
#include <cuda_runtime.h>
#include <cuda_bf16.h>

// ChamferLoss R8: R7 structure, spill-free + higher occupancy.
// regs=248/L1=8.6% showed R2/R7 were spill-stalled (fma pipe 31% busy).
// Changes: RG 8->4 (halves packed-p register block), THREADS 256->512
// (4 warps/SMSP for latency hiding), rmin split into independent lo/hi
// chains. Math identical: u=0.5*d^2 via packed f32x2 FMA, sqrt hoisted
// outside mins, SMEM atomicMin colmin merge, fused deterministic reduction.

#define NPTS    1024
#define THREADS 512
#define NWARPS  16
#define ROWS_PER_WARP 64
#define RG      4
#define CB_MAX  128

typedef unsigned long long ull;

#define PACK2(d, lo, hi) \
    asm("mov.b64 %0, {%1,%2};" : "=l"(d) : "f"(lo), "f"(hi))
#define UNPACK2(lo, hi, s) \
    asm("mov.b64 {%0,%1}, %2;" : "=f"(lo), "=f"(hi) : "l"(s))
#define FMA2(d, a, b, c) \
    asm("fma.rn.f32x2 %0, %1, %2, %3;" : "=l"(d) : "l"(a), "l"(b), "l"(c))
#define ADD2(d, a, b) \
    asm("add.rn.f32x2 %0, %1, %2;" : "=l"(d) : "l"(a), "l"(b))

__device__ float g_partials[CB_MAX];
__device__ int   g_done;   // zero-init; reset by last CTA each run

__global__ __launch_bounds__(THREADS, 1)
void chamfer_pair_kernel(const float* __restrict__ p, const float* __restrict__ q,
                         float* __restrict__ out, int cb_count) {
    __shared__ __align__(16) float qx_s[NPTS], qy_s[NPTS], qz_s[NPTS], qs_s[NPTS];
    __shared__ __align__(16) float px_s[NPTS], py_s[NPTS], pz_s[NPTS], ps_s[NPTS];
    __shared__ unsigned colmin_sh[NPTS];
    __shared__ float warp_rowsum[NWARPS];
    __shared__ float warp_colsum[NWARPS];
    __shared__ int sh_last;

    const int cb  = blockIdx.x;
    const int tid = threadIdx.x;
    const float4* __restrict__ qp = reinterpret_cast<const float4*>(q) + (size_t)cb * NPTS;
    const float4* __restrict__ pp = reinterpret_cast<const float4*>(p) + (size_t)cb * NPTS;

    // Stage both point sets (SoA). p pre-negated; half squared norms precomputed.
    for (int i = tid; i < NPTS; i += THREADS) {
        float4 v = qp[i];
        qx_s[i] = v.y; qy_s[i] = v.z; qz_s[i] = v.w;
        qs_s[i] = 0.5f * (v.y * v.y + v.z * v.z + v.w * v.w);
        float4 u = pp[i];
        px_s[i] = -u.y; py_s[i] = -u.z; pz_s[i] = -u.w;
        ps_s[i] = 0.5f * (u.y * u.y + u.z * u.z + u.w * u.w);
        colmin_sh[i] = 0x7f800000u;  // +inf bits
    }
    __syncthreads();

    const int warp = tid >> 5;
    const int lane = tid & 31;
    const float INF = __int_as_float(0x7f800000);

    // Lane owns columns (j2*64 + lane*2 + {0,1}), j2 = 0..15.
    float colmin[32];
    #pragma unroll
    for (int j = 0; j < 32; ++j) colmin[j] = INF;

    float rowsum = 0.0f;
    const int row0 = warp * ROWS_PER_WARP;

    for (int rg = 0; rg < ROWS_PER_WARP; rg += RG) {
        ull pnx2[RG], pny2[RG], pnz2[RG], psq2[RG];
        float rmin_lo[RG], rmin_hi[RG];
        #pragma unroll
        for (int r = 0; r < RG; ++r) {
            int row = row0 + rg + r;
            float a = px_s[row], b = py_s[row], c = pz_s[row], d = ps_s[row];
            PACK2(pnx2[r], a, a);
            PACK2(pny2[r], b, b);
            PACK2(pnz2[r], c, c);
            PACK2(psq2[r], d, d);
            rmin_lo[r] = INF;
            rmin_hi[r] = INF;
        }
        #pragma unroll
        for (int j2 = 0; j2 < 16; ++j2) {
            const int base = (j2 << 6) + (lane << 1);   // 8B-aligned
            ull xx2 = *reinterpret_cast<const ull*>(qx_s + base);
            ull yy2 = *reinterpret_cast<const ull*>(qy_s + base);
            ull zz2 = *reinterpret_cast<const ull*>(qz_s + base);
            ull ss2 = *reinterpret_cast<const ull*>(qs_s + base);
            #pragma unroll
            for (int r = 0; r < RG; ++r) {
                ull acc;
                ADD2(acc, ss2, psq2[r]);          // 0.5|q|^2 + 0.5|p|^2 (2 cols)
                FMA2(acc, pnx2[r], xx2, acc);     // - px*qx
                FMA2(acc, pny2[r], yy2, acc);
                FMA2(acc, pnz2[r], zz2, acc);     // acc = 0.5*d2 for 2 columns
                float u0, u1;
                UNPACK2(u0, u1, acc);
                colmin[2 * j2]     = fminf(colmin[2 * j2],     u0);
                colmin[2 * j2 + 1] = fminf(colmin[2 * j2 + 1], u1);
                rmin_lo[r] = fminf(rmin_lo[r], u0);   // independent chains
                rmin_hi[r] = fminf(rmin_hi[r], u1);
            }
        }
        // Row mins across lanes; one sqrt per row.
        #pragma unroll
        for (int r = 0; r < RG; ++r) {
            float m = fminf(rmin_lo[r], rmin_hi[r]);
            #pragma unroll
            for (int off = 16; off > 0; off >>= 1)
                m = fminf(m, __shfl_xor_sync(0xffffffffu, m, off));
            rowsum += sqrtf(fmaxf(2.0f * m, 0.0f) + 1e-12f);  // same on all lanes
        }
    }

    // Merge per-warp column mins (clamped >= 0 -> uint order == float order).
    #pragma unroll
    for (int j2 = 0; j2 < 16; ++j2) {
        #pragma unroll
        for (int k = 0; k < 2; ++k) {
            int c = (j2 << 6) + (lane << 1) + k;
            float v = fmaxf(colmin[2 * j2 + k], 0.0f);
            atomicMin(&colmin_sh[c], __float_as_uint(v));
        }
    }
    if (lane == 0) warp_rowsum[warp] = rowsum;
    __syncthreads();

    // Column distance sums.
    float csum = 0.0f;
    for (int i = tid; i < NPTS; i += THREADS) {
        float v = __uint_as_float(colmin_sh[i]);  // already clamped >= 0
        csum += sqrtf(2.0f * v + 1e-12f);
    }
    #pragma unroll
    for (int off = 16; off > 0; off >>= 1)
        csum += __shfl_xor_sync(0xffffffffu, csum, off);
    if (lane == 0) warp_colsum[warp] = csum;
    __syncthreads();

    // Per-CTA total + done-ticket.
    if (tid == 0) {
        float total = 0.0f;
        #pragma unroll
        for (int w = 0; w < NWARPS; ++w) total += warp_rowsum[w] + warp_colsum[w];
        g_partials[cb] = total;
        __threadfence();                       // partial visible before ticket
        int prev = atomicAdd(&g_done, 1);
        sh_last = (prev == cb_count - 1) ? 1 : 0;
    }
    __syncthreads();

    // Last CTA: deterministic fixed-order final reduction over all pairs.
    if (sh_last) {
        __threadfence();                       // observe all partials (L2)
        float v = (tid < cb_count) ? __ldcg(&g_partials[tid]) : 0.0f;
        #pragma unroll
        for (int off = 16; off > 0; off >>= 1)
            v += __shfl_xor_sync(0xffffffffu, v, off);
        if (lane == 0) warp_rowsum[warp] = v;  // reuse as scratch
        __syncthreads();
        if (tid == 0) {
            float tot = 0.0f;
            #pragma unroll
            for (int w = 0; w < NWARPS; ++w) tot += warp_rowsum[w];
            out[0] = tot;
            g_done = 0;                        // reset for next graph replay
        }
    }
}

extern "C" void kernel_launch(void* const* d_in, const int* in_sizes, int n_in,
                              void* d_out, int out_size) {
    const float* p = (const float*)d_in[0];
    const float* q = (const float*)d_in[1];
    float* out = (float*)d_out;

    int cb = in_sizes[0] / (NPTS * 4);   // = 128 for (2,64,1024,4)
    if (cb > CB_MAX) cb = CB_MAX;

    chamfer_pair_kernel<<<cb, THREADS>>>(p, q, out, cb);
}

// round 9
// speedup vs baseline: 1.4404x; 1.4404x over previous
#include <cuda_runtime.h>
#include <cuda_bf16.h>

// ChamferLoss R9: spill-free configuration.
// 384 threads (reg cap 170, 3 warps/SMSP), RG=4 row group (packed-p block
// 32 regs), 4 columns per inner iteration via LDS.128. Math unchanged:
// u = 0.5*d^2 via packed f32x2 FMA (norms folded into accumulator init),
// sqrt hoisted outside the mins, SMEM atomicMin column-min merge, fused
// deterministic final reduction via done-ticket. One CTA per (c,b) pair.

#define NPTS    1024
#define THREADS 384
#define NWARPS  12
#define RG      4
#define NGROUPS (NPTS / RG)   // 256 four-row groups
#define CB_MAX  128

typedef unsigned long long ull;

#define PACK2(d, lo, hi) \
    asm("mov.b64 %0, {%1,%2};" : "=l"(d) : "f"(lo), "f"(hi))
#define UNPACK2(lo, hi, s) \
    asm("mov.b64 {%0,%1}, %2;" : "=f"(lo), "=f"(hi) : "l"(s))
#define FMA2(d, a, b, c) \
    asm("fma.rn.f32x2 %0, %1, %2, %3;" : "=l"(d) : "l"(a), "l"(b), "l"(c))
#define ADD2(d, a, b) \
    asm("add.rn.f32x2 %0, %1, %2;" : "=l"(d) : "l"(a), "l"(b))

__device__ float g_partials[CB_MAX];
__device__ int   g_done;   // zero-init; reset by last CTA each run

__global__ __launch_bounds__(THREADS, 1)
void chamfer_pair_kernel(const float* __restrict__ p, const float* __restrict__ q,
                         float* __restrict__ out, int cb_count) {
    __shared__ __align__(16) float qx_s[NPTS], qy_s[NPTS], qz_s[NPTS], qs_s[NPTS];
    __shared__ __align__(16) float px_s[NPTS], py_s[NPTS], pz_s[NPTS], ps_s[NPTS];
    __shared__ unsigned colmin_sh[NPTS];
    __shared__ float warp_rowsum[NWARPS];
    __shared__ float warp_colsum[NWARPS];
    __shared__ int sh_last;

    const int cb  = blockIdx.x;
    const int tid = threadIdx.x;
    const float4* __restrict__ qp = reinterpret_cast<const float4*>(q) + (size_t)cb * NPTS;
    const float4* __restrict__ pp = reinterpret_cast<const float4*>(p) + (size_t)cb * NPTS;

    // Stage both point sets (SoA). p pre-negated; half squared norms precomputed.
    for (int i = tid; i < NPTS; i += THREADS) {
        float4 v = qp[i];
        qx_s[i] = v.y; qy_s[i] = v.z; qz_s[i] = v.w;
        qs_s[i] = 0.5f * (v.y * v.y + v.z * v.z + v.w * v.w);
        float4 u = pp[i];
        px_s[i] = -u.y; py_s[i] = -u.z; pz_s[i] = -u.w;
        ps_s[i] = 0.5f * (u.y * u.y + u.z * u.z + u.w * u.w);
        colmin_sh[i] = 0x7f800000u;  // +inf bits
    }
    __syncthreads();

    const int warp = tid >> 5;
    const int lane = tid & 31;
    const float INF = __int_as_float(0x7f800000);

    // Lane owns columns (j4*128 + lane*4 + {0..3}), j4 = 0..7  -> colmin[32].
    float colmin[32];
    #pragma unroll
    for (int j = 0; j < 32; ++j) colmin[j] = INF;

    float rowsum = 0.0f;

    // 4-row groups round-robin over 12 warps (22 vs 21 groups: 2% imbalance).
    for (int g = warp; g < NGROUPS; g += NWARPS) {
        const int row0 = g * RG;
        ull pnx2[RG], pny2[RG], pnz2[RG], psq2[RG];
        float rmin[RG];
        #pragma unroll
        for (int r = 0; r < RG; ++r) {
            int row = row0 + r;
            float a = px_s[row], b = py_s[row], c = pz_s[row], d = ps_s[row];
            PACK2(pnx2[r], a, a);
            PACK2(pny2[r], b, b);
            PACK2(pnz2[r], c, c);
            PACK2(psq2[r], d, d);
            rmin[r] = INF;
        }
        #pragma unroll
        for (int j4 = 0; j4 < 8; ++j4) {
            const int base = (j4 << 7) + (lane << 2);   // 16B-aligned
            ulonglong2 xx = *reinterpret_cast<const ulonglong2*>(qx_s + base);
            ulonglong2 yy = *reinterpret_cast<const ulonglong2*>(qy_s + base);
            ulonglong2 zz = *reinterpret_cast<const ulonglong2*>(qz_s + base);
            ulonglong2 ss = *reinterpret_cast<const ulonglong2*>(qs_s + base);
            #pragma unroll
            for (int r = 0; r < RG; ++r) {
                ull a01, a23;
                ADD2(a01, ss.x, psq2[r]);          // 0.5|q|^2 + 0.5|p|^2
                ADD2(a23, ss.y, psq2[r]);
                FMA2(a01, pnx2[r], xx.x, a01);     // - px*qx
                FMA2(a23, pnx2[r], xx.y, a23);
                FMA2(a01, pny2[r], yy.x, a01);
                FMA2(a23, pny2[r], yy.y, a23);
                FMA2(a01, pnz2[r], zz.x, a01);     // = 0.5*d2, 4 columns
                FMA2(a23, pnz2[r], zz.y, a23);
                float u0, u1, u2, u3;
                UNPACK2(u0, u1, a01);
                UNPACK2(u2, u3, a23);
                colmin[4 * j4 + 0] = fminf(colmin[4 * j4 + 0], u0);
                colmin[4 * j4 + 1] = fminf(colmin[4 * j4 + 1], u1);
                colmin[4 * j4 + 2] = fminf(colmin[4 * j4 + 2], u2);
                colmin[4 * j4 + 3] = fminf(colmin[4 * j4 + 3], u3);
                rmin[r] = fminf(rmin[r], fminf(fminf(u0, u1), fminf(u2, u3)));
            }
        }
        // Row mins across lanes; one sqrt per row.
        #pragma unroll
        for (int r = 0; r < RG; ++r) {
            float m = rmin[r];
            #pragma unroll
            for (int off = 16; off > 0; off >>= 1)
                m = fminf(m, __shfl_xor_sync(0xffffffffu, m, off));
            rowsum += sqrtf(fmaxf(2.0f * m, 0.0f) + 1e-12f);  // same on all lanes
        }
    }

    // Merge per-warp column mins (clamped >= 0 -> uint order == float order).
    #pragma unroll
    for (int j4 = 0; j4 < 8; ++j4) {
        #pragma unroll
        for (int k = 0; k < 4; ++k) {
            int c = (j4 << 7) + (lane << 2) + k;
            float v = fmaxf(colmin[4 * j4 + k], 0.0f);
            atomicMin(&colmin_sh[c], __float_as_uint(v));
        }
    }
    if (lane == 0) warp_rowsum[warp] = rowsum;
    __syncthreads();

    // Column distance sums.
    float csum = 0.0f;
    for (int i = tid; i < NPTS; i += THREADS) {
        float v = __uint_as_float(colmin_sh[i]);  // already clamped >= 0
        csum += sqrtf(2.0f * v + 1e-12f);
    }
    #pragma unroll
    for (int off = 16; off > 0; off >>= 1)
        csum += __shfl_xor_sync(0xffffffffu, csum, off);
    if (lane == 0) warp_colsum[warp] = csum;
    __syncthreads();

    // Per-CTA total + done-ticket.
    if (tid == 0) {
        float total = 0.0f;
        #pragma unroll
        for (int w = 0; w < NWARPS; ++w) total += warp_rowsum[w] + warp_colsum[w];
        g_partials[cb] = total;
        __threadfence();                       // partial visible before ticket
        int prev = atomicAdd(&g_done, 1);
        sh_last = (prev == cb_count - 1) ? 1 : 0;
    }
    __syncthreads();

    // Last CTA: deterministic fixed-order final reduction over all pairs.
    if (sh_last) {
        __threadfence();                       // observe all partials (L2)
        float v = (tid < cb_count) ? __ldcg(&g_partials[tid]) : 0.0f;
        #pragma unroll
        for (int off = 16; off > 0; off >>= 1)
            v += __shfl_xor_sync(0xffffffffu, v, off);
        if (lane == 0) warp_rowsum[warp] = v;  // reuse as scratch
        __syncthreads();
        if (tid == 0) {
            float tot = 0.0f;
            #pragma unroll
            for (int w = 0; w < NWARPS; ++w) tot += warp_rowsum[w];
            out[0] = tot;
            g_done = 0;                        // reset for next graph replay
        }
    }
}

extern "C" void kernel_launch(void* const* d_in, const int* in_sizes, int n_in,
                              void* d_out, int out_size) {
    const float* p = (const float*)d_in[0];
    const float* q = (const float*)d_in[1];
    float* out = (float*)d_out;

    int cb = in_sizes[0] / (NPTS * 4);   // = 128 for (2,64,1024,4)
    if (cb > CB_MAX) cb = CB_MAX;

    chamfer_pair_kernel<<<cb, THREADS>>>(p, q, out, cb);
}